// round 8
// baseline (speedup 1.0000x reference)
#include <cuda_runtime.h>
#include <cstdint>

#define BB   32
#define C1   64
#define GG   256
#define HW   122
#define W0IN 128
#define CLU  4      // width slices (CTAs) per batch
#define WSL  31     // nominal slice width (last slice = 29)
#define HSTR 36     // hbuf row stride (floats), >= 34

typedef unsigned long long u64;

// ---------------- scratch (static __device__: allocation-free) ----------------
__device__ float g_feat[BB * C1 * HW * HW];        // ~122 MB
// gates incl. both biases, layout [b][h][gate][w] -> one contiguous row-block per (b,h)
__device__ float g_i2s[BB * HW * GG * HW];         // ~488 MB

// ---------------- math helpers ----------------
__device__ __forceinline__ float tanha(float x) {
    float y;
    asm("tanh.approx.f32 %0, %1;" : "=f"(y) : "f"(x));
    return y;
}
__device__ __forceinline__ float sigmf(float x) {
    return 0.5f * tanha(0.5f * x) + 0.5f;
}
__device__ __forceinline__ u64 pk2(float lo, float hi) {
    u64 r;
    asm("mov.b64 %0, {%1, %2};" : "=l"(r) : "f"(lo), "f"(hi));
    return r;
}
__device__ __forceinline__ void fma2(u64& d, u64 a, u64 b) {
    asm("fma.rn.f32x2 %0, %1, %2, %0;" : "+l"(d) : "l"(a), "l"(b));
}
__device__ __forceinline__ void unpk2(u64 v, float& lo, float& hi) {
    asm("mov.b64 {%0, %1}, %2;" : "=f"(lo), "=f"(hi) : "l"(v));
}
__device__ __forceinline__ uint32_t smem_u32(const void* p) {
    uint32_t a;
    asm("{ .reg .u64 tt; cvta.to.shared.u64 tt, %1; cvt.u32.u64 %0, tt; }"
        : "=r"(a) : "l"(p));
    return a;
}
// store a float into peer CTA's smem (same offset), ordered by the cluster barrier
__device__ __forceinline__ void st_dsmem(uint32_t laddr, uint32_t rank, float v) {
    asm volatile(
        "{ .reg .b32 ra; mapa.shared::cluster.u32 ra, %0, %1; "
        "st.shared::cluster.f32 [ra], %2; }"
        :: "r"(laddr), "r"(rank), "f"(v) : "memory");
}

// ---------------- conv1: 7x7 valid, [B,1,128,128] -> [B,64,122,122] ----------------
__global__ __launch_bounds__(256) void conv1_kernel(
    const float* __restrict__ x, const float* __restrict__ w1, const float* __restrict__ b1)
{
    __shared__ float xs[7][136];
    __shared__ float ws[C1 * 49];
    __shared__ float bs[C1];

    int bh = blockIdx.x;
    int b = bh / HW, h = bh % HW;
    int t = threadIdx.x;

    for (int i = t; i < C1 * 49; i += 256) ws[i] = w1[i];
    if (t < C1) bs[t] = b1[t];
    for (int i = t; i < 7 * 136; i += 256) {
        int r = i / 136, cw = i % 136;
        xs[r][cw] = (cw < W0IN) ? x[(b * W0IN + (h + r)) * W0IN + cw] : 0.f;
    }
    __syncthreads();

    for (int task = t; task < C1 * 32; task += 256) {
        int c = task >> 5;
        int wt = task & 31;
        int w0 = wt * 4;
        float a0 = 0.f, a1 = 0.f, a2 = 0.f, a3 = 0.f;
#pragma unroll
        for (int kh = 0; kh < 7; kh++) {
            float4 va = *(const float4*)&xs[kh][w0];
            float4 vb = *(const float4*)&xs[kh][w0 + 4];
            float2 vc = *(const float2*)&xs[kh][w0 + 8];
            float f[10] = {va.x, va.y, va.z, va.w, vb.x, vb.y, vb.z, vb.w, vc.x, vc.y};
            const float* wr = &ws[c * 49 + kh * 7];
#pragma unroll
            for (int kw = 0; kw < 7; kw++) {
                float wv = wr[kw];
                a0 += wv * f[kw];
                a1 += wv * f[kw + 1];
                a2 += wv * f[kw + 2];
                a3 += wv * f[kw + 3];
            }
        }
        float bb = bs[c];
        int base = ((b * C1 + c) * HW + h) * HW + w0;
        if (w0 + 0 < HW) g_feat[base + 0] = a0 + bb;
        if (w0 + 1 < HW) g_feat[base + 1] = a1 + bb;
        if (w0 + 2 < HW) g_feat[base + 2] = a2 + bb;
        if (w0 + 3 < HW) g_feat[base + 3] = a3 + bb;
    }
}

// ---------------- i2s: (1,3) conv SAME-width; output layout [b][h][gate][w] --------
__global__ __launch_bounds__(256) void i2s_kernel(
    const float* __restrict__ w, const float* __restrict__ bi, const float* __restrict__ bs2)
{
    extern __shared__ float sm[];
    float* fp = sm;                        // [64][124] padded feat row
    float* ws = sm + C1 * 124 + 8;         // [128][192]
    float* bc = ws + 128 * 192;            // [128]

    int bx = blockIdx.x;
    int half = bx & 1;
    int bh = bx >> 1;
    int b = bh / HW, h = bh % HW;
    int t = threadIdx.x;

    for (int i = t; i < C1 * 124; i += 256) {
        int c = i / 124, cw = i % 124;
        fp[i] = (cw >= 1 && cw <= HW) ? g_feat[((b * C1 + c) * HW + h) * HW + (cw - 1)] : 0.f;
    }
    if (t < 8) fp[C1 * 124 + t] = 0.f;
    for (int i = t; i < 128 * 192; i += 256) ws[i] = w[(half * 128) * 192 + i];
    if (t < 128) {
        int og = half * 128 + t;
        bc[t] = bi[og] + bs2[og];
    }
    __syncthreads();

    int wt = t & 31;
    int rt0 = t >> 5;
    int w0 = wt * 4;
    bool active = (w0 < HW);

    for (int pass = 0; pass < 2; pass++) {
        int oc0 = (rt0 + 8 * pass) * 8;
        if (active) {
            u64 aA[8], aB[8];
#pragma unroll
            for (int i = 0; i < 8; i++) { aA[i] = 0ull; aB[i] = 0ull; }
#pragma unroll 2
            for (int c = 0; c < C1; c++) {
                const float* fr = &fp[c * 124 + w0];
                float4 va = *(const float4*)fr;
                float2 vb = *(const float2*)(fr + 4);
                u64 P0 = pk2(va.x, va.y), P1 = pk2(va.y, va.z), P2 = pk2(va.z, va.w);
                u64 P3 = pk2(va.w, vb.x), P4 = pk2(vb.x, vb.y);
                const float* wr = &ws[oc0 * 192 + c * 3];
#pragma unroll
                for (int i = 0; i < 8; i++) {
                    float wv0 = wr[i * 192 + 0];
                    float wv1 = wr[i * 192 + 1];
                    float wv2 = wr[i * 192 + 2];
                    u64 s0 = pk2(wv0, wv0), s1 = pk2(wv1, wv1), s2 = pk2(wv2, wv2);
                    fma2(aA[i], s0, P0);  fma2(aB[i], s0, P2);
                    fma2(aA[i], s1, P1);  fma2(aB[i], s1, P3);
                    fma2(aA[i], s2, P2);  fma2(aB[i], s2, P4);
                }
            }
#pragma unroll
            for (int i = 0; i < 8; i++) {
                int ocl = oc0 + i;
                int og = half * 128 + ocl;
                float bb = bc[ocl];
                float r0, r1, r2, r3;
                unpk2(aA[i], r0, r1);
                unpk2(aB[i], r2, r3);
                // NEW layout: [b][h][gate][w]
                int base = ((b * HW + h) * GG + og) * HW + w0;
                if (w0 + 0 < HW) g_i2s[base + 0] = r0 + bb;
                if (w0 + 1 < HW) g_i2s[base + 1] = r1 + bb;
                if (w0 + 2 < HW) g_i2s[base + 2] = r2 + bb;
                if (w0 + 3 < HW) g_i2s[base + 3] = r3 + bb;
            }
        }
    }
}

// ---------------- persistent scan v5: row-pipelined gate prefetch ----------------
// Cluster = batch (4 CTAs, slices 31/31/31/29). 512 threads, 1 CTA/SM.
// Paired u64 weights in smem (zero weight-pack ALU); DSMEM halo push; gate
// fetch for row r+1 issued before row r's GEMM (two GEMMs of slack), from the
// streaming-friendly [b][h][gate][w] layout.
__global__ __launch_bounds__(512, 1) __cluster_dims__(CLU, 1, 1)
void scan_kernel(const float* __restrict__ ws2, float* __restrict__ out)
{
    extern __shared__ float sm[];
    u64*   wP   = (u64*)sm;                   // [192][128] paired weights (196.6 KB)
    float* hbuf = sm + 192 * GG;              // [2][64][HSTR]

    int t  = threadIdx.x;
    int bx = blockIdx.x;
    int b  = bx / CLU;
    int jr = bx % CLU;
    int ws_off = jr * WSL;
    int Ws = (jr == CLU - 1) ? (HW - (CLU - 1) * WSL) : WSL;   // 31/31/31/29

    // paired weights: wP[k][p] = (ws2[2p][k], ws2[2p+1][k])
    for (int i = t; i < 192 * 128; i += 512) {
        int k = i >> 7, p = i & 127;
        wP[i] = pk2(ws2[(2 * p) * 192 + k], ws2[(2 * p + 1) * 192 + k]);
    }
    for (int i = t; i < 2 * C1 * HSTR; i += 512) hbuf[i] = 0.f;
    __syncthreads();

    int wid  = t >> 5;            // warp -> channel group (4 channels)
    int lane = t & 31;            // lane -> local w
    int ch0  = wid * 4;
    int wg   = ws_off + lane;     // global w
    bool active = (lane < Ws);

    uint32_t hbuf_su = smem_u32(hbuf);

    float cst[4] = {0.f, 0.f, 0.f, 0.f};

    // ---- preload gates for row 0 ([b][h][gate][w] layout)
    float nxt[4][4];
    if (active) {
        const float* rb = &g_i2s[((size_t)(b * HW + 0) * GG) * HW + wg];
#pragma unroll
        for (int ty = 0; ty < 4; ty++)
#pragma unroll
            for (int cc = 0; cc < 4; cc++)
                nxt[ty][cc] = __ldcg(rb + (ty * 64 + ch0 + cc) * HW);
    }

    for (int r = 0; r < HW; r++) {
        int pb = r & 1;
        int cb = pb ^ 1;
        const float* hp = hbuf + pb * C1 * HSTR;
        float*       hn = hbuf + cb * C1 * HSTR;
        uint32_t hn_su = hbuf_su + (uint32_t)(cb * C1 * HSTR) * 4u;

        // rotate pipeline: consume cur this row, start loading r+1 now
        float cur[4][4];
#pragma unroll
        for (int ty = 0; ty < 4; ty++)
#pragma unroll
            for (int cc = 0; cc < 4; cc++) cur[ty][cc] = nxt[ty][cc];

        if (active && r + 1 < HW) {
            const float* rb = &g_i2s[((size_t)(b * HW + (r + 1)) * GG) * HW + wg];
#pragma unroll
            for (int ty = 0; ty < 4; ty++)
#pragma unroll
                for (int cc = 0; cc < 4; cc++)
                    nxt[ty][cc] = __ldcg(rb + (ty * 64 + ch0 + cc) * HW);
        }

        // ---- GEMM: gates[ty][ch0..ch0+3] at w = wg
        u64 aA[4], aB[4];
#pragma unroll
        for (int ty = 0; ty < 4; ty++) { aA[ty] = 0ull; aB[ty] = 0ull; }

#pragma unroll 4
        for (int c = 0; c < C1; c++) {
            const float* hr = &hp[c * HSTR + lane];   // h(wg-1), h(wg), h(wg+1)
            float h0 = hr[0], h1 = hr[1], h2 = hr[2];
            u64 s0 = pk2(h0, h0), s1 = pk2(h1, h1), s2 = pk2(h2, h2);
            const u64* wk = &wP[(c * 3) * 128 + (wid << 1)];
#pragma unroll
            for (int ty = 0; ty < 4; ty++) {
                ulonglong2 u0 = *(const ulonglong2*)(wk + ty * 32);
                ulonglong2 u1 = *(const ulonglong2*)(wk + ty * 32 + 128);
                ulonglong2 u2 = *(const ulonglong2*)(wk + ty * 32 + 256);
                fma2(aA[ty], u0.x, s0);  fma2(aB[ty], u0.y, s0);
                fma2(aA[ty], u1.x, s1);  fma2(aB[ty], u1.y, s1);
                fma2(aA[ty], u2.x, s2);  fma2(aB[ty], u2.y, s2);
            }
        }

        // ---- LSTM epilogue
        if (active) {
            float gate[4][4];
#pragma unroll
            for (int ty = 0; ty < 4; ty++) {
                unpk2(aA[ty], gate[ty][0], gate[ty][1]);
                unpk2(aB[ty], gate[ty][2], gate[ty][3]);
            }
#pragma unroll
            for (int cc = 0; cc < 4; cc++) {
                float go = gate[0][cc] + cur[0][cc];
                float gf = gate[1][cc] + cur[1][cc];
                float gi = gate[2][cc] + cur[2][cc];
                float gg = gate[3][cc] + cur[3][cc];
                float cn = sigmf(gf) * cst[cc] + sigmf(gi) * tanha(gg);
                float hv = sigmf(go) * tanha(cn);
                cst[cc] = cn;
                int ch = ch0 + cc;
                hn[ch * HSTR + lane + 1] = hv;                          // local
                out[((b * C1 + ch) * HW + r) * HW + wg] = hv;
                if (lane == 0 && jr > 0)
                    st_dsmem(hn_su + (uint32_t)(ch * HSTR + 32) * 4u, jr - 1, hv);
                if (lane == Ws - 1 && jr < CLU - 1)
                    st_dsmem(hn_su + (uint32_t)(ch * HSTR + 0) * 4u, jr + 1, hv);
            }
        }

        // one barrier per row: orders local STS + remote DSMEM stores cluster-wide
        asm volatile("barrier.cluster.arrive.aligned;" ::: "memory");
        asm volatile("barrier.cluster.wait.aligned;"   ::: "memory");
    }
}

// ---------------- launch ----------------
extern "C" void kernel_launch(void* const* d_in, const int* in_sizes, int n_in,
                              void* d_out, int out_size)
{
    const float* x   = (const float*)d_in[0];
    const float* c1w = (const float*)d_in[1];
    const float* c1b = (const float*)d_in[2];
    const float* i2w = (const float*)d_in[3];
    const float* i2b = (const float*)d_in[4];
    const float* s2w = (const float*)d_in[5];
    const float* s2b = (const float*)d_in[6];
    float* out = (float*)d_out;

    const int i2s_smem  = (C1 * 124 + 8 + 128 * 192 + 128) * sizeof(float);     // ~130.6 KB
    const int scan_smem = 192 * 128 * 8 + 2 * C1 * HSTR * 4;                    // ~210 KB
    cudaFuncSetAttribute(i2s_kernel,  cudaFuncAttributeMaxDynamicSharedMemorySize, i2s_smem);
    cudaFuncSetAttribute(scan_kernel, cudaFuncAttributeMaxDynamicSharedMemorySize, scan_smem);

    conv1_kernel<<<BB * HW, 256>>>(x, c1w, c1b);
    i2s_kernel<<<BB * HW * 2, 256, i2s_smem>>>(i2w, i2b, s2b);
    scan_kernel<<<BB * CLU, 512, scan_smem>>>(s2w, out);
}

// round 9
// speedup vs baseline: 1.2234x; 1.2234x over previous
#include <cuda_runtime.h>
#include <cstdint>

#define BB   32
#define C1   64
#define GG   256
#define HW   122
#define W0IN 128
#define CLU  4      // width slices (CTAs) per batch
#define WSL  31     // nominal slice width (last slice = 29)
#define HSTR 36     // scan hbuf row stride (floats), >= 34
#define FSTR 136    // i2s feat smem stride (==8 mod 32 -> conflict-free B frags)
#define WSTR 196    // i2s weight smem stride (==4 mod 32 -> conflict-free A frags)

typedef unsigned long long u64;

// ---------------- scratch (static __device__: allocation-free) ----------------
__device__ float g_feat[BB * C1 * HW * HW];        // ~122 MB
__device__ float g_i2s[BB * GG * HW * HW];         // ~488 MB, layout [b][gate][h][w]

// ---------------- math helpers ----------------
__device__ __forceinline__ float tanha(float x) {
    float y;
    asm("tanh.approx.f32 %0, %1;" : "=f"(y) : "f"(x));
    return y;
}
__device__ __forceinline__ float sigmf(float x) {
    return 0.5f * tanha(0.5f * x) + 0.5f;
}
__device__ __forceinline__ u64 pk2(float lo, float hi) {
    u64 r;
    asm("mov.b64 %0, {%1, %2};" : "=l"(r) : "f"(lo), "f"(hi));
    return r;
}
__device__ __forceinline__ void fma2(u64& d, u64 a, u64 b) {
    asm("fma.rn.f32x2 %0, %1, %2, %0;" : "+l"(d) : "l"(a), "l"(b));
}
__device__ __forceinline__ void unpk2(u64 v, float& lo, float& hi) {
    asm("mov.b64 {%0, %1}, %2;" : "=f"(lo), "=f"(hi) : "l"(v));
}
__device__ __forceinline__ uint32_t smem_u32(const void* p) {
    uint32_t a;
    asm("{ .reg .u64 tt; cvta.to.shared.u64 tt, %1; cvt.u32.u64 %0, tt; }"
        : "=r"(a) : "l"(p));
    return a;
}
__device__ __forceinline__ void st_dsmem(uint32_t laddr, uint32_t rank, float v) {
    asm volatile(
        "{ .reg .b32 ra; mapa.shared::cluster.u32 ra, %0, %1; "
        "st.shared::cluster.f32 [ra], %2; }"
        :: "r"(laddr), "r"(rank), "f"(v) : "memory");
}
__device__ __forceinline__ float tf32r(float x) {
    uint32_t u;
    asm("cvt.rna.tf32.f32 %0, %1;" : "=r"(u) : "f"(x));
    return __uint_as_float(u);
}
__device__ __forceinline__ void mma_tf32(float* d,
    uint32_t a0, uint32_t a1, uint32_t a2, uint32_t a3, uint32_t b0, uint32_t b1)
{
    asm volatile(
        "mma.sync.aligned.m16n8k8.row.col.f32.tf32.tf32.f32 "
        "{%0,%1,%2,%3}, {%4,%5,%6,%7}, {%8,%9}, {%0,%1,%2,%3};"
        : "+f"(d[0]), "+f"(d[1]), "+f"(d[2]), "+f"(d[3])
        : "r"(a0), "r"(a1), "r"(a2), "r"(a3), "r"(b0), "r"(b1));
}

// ---------------- conv1: 7x7 valid, [B,1,128,128] -> [B,64,122,122] ----------------
__global__ __launch_bounds__(256) void conv1_kernel(
    const float* __restrict__ x, const float* __restrict__ w1, const float* __restrict__ b1)
{
    __shared__ float xs[7][136];
    __shared__ float ws[C1 * 49];
    __shared__ float bs[C1];

    int bh = blockIdx.x;
    int b = bh / HW, h = bh % HW;
    int t = threadIdx.x;

    for (int i = t; i < C1 * 49; i += 256) ws[i] = w1[i];
    if (t < C1) bs[t] = b1[t];
    for (int i = t; i < 7 * 136; i += 256) {
        int r = i / 136, cw = i % 136;
        xs[r][cw] = (cw < W0IN) ? x[(b * W0IN + (h + r)) * W0IN + cw] : 0.f;
    }
    __syncthreads();

    for (int task = t; task < C1 * 32; task += 256) {
        int c = task >> 5;
        int wt = task & 31;
        int w0 = wt * 4;
        float a0 = 0.f, a1 = 0.f, a2 = 0.f, a3 = 0.f;
#pragma unroll
        for (int kh = 0; kh < 7; kh++) {
            float4 va = *(const float4*)&xs[kh][w0];
            float4 vb = *(const float4*)&xs[kh][w0 + 4];
            float2 vc = *(const float2*)&xs[kh][w0 + 8];
            float f[10] = {va.x, va.y, va.z, va.w, vb.x, vb.y, vb.z, vb.w, vc.x, vc.y};
            const float* wr = &ws[c * 49 + kh * 7];
#pragma unroll
            for (int kw = 0; kw < 7; kw++) {
                float wv = wr[kw];
                a0 += wv * f[kw];
                a1 += wv * f[kw + 1];
                a2 += wv * f[kw + 2];
                a3 += wv * f[kw + 3];
            }
        }
        float bb = bs[c];
        int base = ((b * C1 + c) * HW + h) * HW + w0;
        if (w0 + 0 < HW) g_feat[base + 0] = a0 + bb;
        if (w0 + 1 < HW) g_feat[base + 1] = a1 + bb;
        if (w0 + 2 < HW) g_feat[base + 2] = a2 + bb;
        if (w0 + 3 < HW) g_feat[base + 3] = a3 + bb;
    }
}

// ---------------- i2s v2: tf32 tensor-core GEMM per (b,h,half) ----------------
// D[128,128] = W[128,192] @ F[192,128], F[k'][n] read in-place from the padded
// feat row with k' = dx*64 + c (K-permuted so dx is constant within a k-step).
// Warp = one 16-row m-tile x full N=128 (16 n-tiles), 24 k-steps of 8.
__global__ __launch_bounds__(256) void i2s_kernel(
    const float* __restrict__ w, const float* __restrict__ bi, const float* __restrict__ bs2)
{
    extern __shared__ float sm[];
    float* fp  = sm;                     // [64][FSTR] tf32 feat row (left pad col 0)
    float* wsm = sm + C1 * FSTR;         // [128][WSTR] tf32 weights, k-permuted
    float* bc  = wsm + 128 * WSTR;       // [128]

    int bx = blockIdx.x;
    int half = bx & 1;
    int bh = bx >> 1;
    int b = bh / HW, h = bh % HW;
    int t = threadIdx.x;

    for (int i = t; i < C1 * FSTR; i += 256) fp[i] = 0.f;
    __syncthreads();
    for (int i = t; i < C1 * HW; i += 256) {
        int c = i / HW, cw = i % HW;
        fp[c * FSTR + 1 + cw] = tf32r(g_feat[((b * C1 + c) * HW + h) * HW + cw]);
    }
    // wsm[m][k'] = tf32(w[(half*128+m)*192 + c*3+dx]), k' = dx*64 + c
    for (int i = t; i < 128 * 192; i += 256) {
        int m = i / 192, kp = i % 192;
        int dx = kp >> 6, c = kp & 63;
        wsm[m * WSTR + kp] = tf32r(w[(half * 128 + m) * 192 + c * 3 + dx]);
    }
    if (t < 128) {
        int og = half * 128 + t;
        bc[t] = bi[og] + bs2[og];
    }
    __syncthreads();

    int wid  = t >> 5;
    int lane = t & 31;
    int m0 = wid * 16;
    int qr = lane >> 2;       // tid/4 : 0..7  (n within n-tile / A row)
    int q  = lane & 3;        // tid%4 : k within quad

    const float* Ar0 = wsm + (m0 + qr) * WSTR;
    const float* Ar1 = wsm + (m0 + qr + 8) * WSTR;

    float d[16][4];
#pragma unroll
    for (int nt = 0; nt < 16; nt++)
#pragma unroll
        for (int i = 0; i < 4; i++) d[nt][i] = 0.f;

#pragma unroll
    for (int ks = 0; ks < 24; ks++) {
        int dx = ks >> 3;
        int cb = (ks & 7) * 8;            // c base inside this dx block
        int kb = ks * 8;
        uint32_t a0 = __float_as_uint(Ar0[kb + q]);
        uint32_t a1 = __float_as_uint(Ar1[kb + q]);
        uint32_t a2 = __float_as_uint(Ar0[kb + q + 4]);
        uint32_t a3 = __float_as_uint(Ar1[kb + q + 4]);
        const float* B0 = fp + (cb + q) * FSTR + dx + qr;       // + nt*8
        const float* B1 = fp + (cb + q + 4) * FSTR + dx + qr;
#pragma unroll
        for (int nt = 0; nt < 16; nt++) {
            uint32_t b0 = __float_as_uint(B0[nt * 8]);
            uint32_t b1 = __float_as_uint(B1[nt * 8]);
            mma_tf32(d[nt], a0, a1, a2, a3, b0, b1);
        }
    }

    // epilogue: rows m0+qr and m0+qr+8; cols nt*8 + q*2 (+1). HW even -> pair check.
    const int HW2 = HW * HW;
    int og0 = half * 128 + m0 + qr;
    int og1 = og0 + 8;
    float bb0 = bc[m0 + qr];
    float bb1 = bc[m0 + qr + 8];
    float* o0 = &g_i2s[((size_t)(b * GG + og0)) * HW2 + h * HW];
    float* o1 = &g_i2s[((size_t)(b * GG + og1)) * HW2 + h * HW];
#pragma unroll
    for (int nt = 0; nt < 16; nt++) {
        int col = nt * 8 + q * 2;
        if (col < HW) {
            *(float2*)(o0 + col) = make_float2(d[nt][0] + bb0, d[nt][1] + bb0);
            *(float2*)(o1 + col) = make_float2(d[nt][2] + bb1, d[nt][3] + bb1);
        }
    }
}

// ---------------- persistent scan (R7 verbatim: best measured) ----------------
__global__ __launch_bounds__(512, 1) __cluster_dims__(CLU, 1, 1)
void scan_kernel(const float* __restrict__ ws2, float* __restrict__ out)
{
    extern __shared__ float sm[];
    u64*   wP   = (u64*)sm;                   // [192][128] paired weights
    float* hbuf = sm + 192 * GG;              // [2][64][HSTR]

    int t  = threadIdx.x;
    int bx = blockIdx.x;
    int b  = bx / CLU;
    int jr = bx % CLU;
    int ws_off = jr * WSL;
    int Ws = (jr == CLU - 1) ? (HW - (CLU - 1) * WSL) : WSL;

    for (int i = t; i < 192 * 128; i += 512) {
        int k = i >> 7, p = i & 127;
        wP[i] = pk2(ws2[(2 * p) * 192 + k], ws2[(2 * p + 1) * 192 + k]);
    }
    for (int i = t; i < 2 * C1 * HSTR; i += 512) hbuf[i] = 0.f;
    __syncthreads();

    int wid  = t >> 5;
    int lane = t & 31;
    int ch0  = wid * 4;
    int wg   = ws_off + lane;
    bool active = (lane < Ws);

    uint32_t hbuf_su = smem_u32(hbuf);

    float cst[4] = {0.f, 0.f, 0.f, 0.f};
    const int HW2 = HW * HW;

    for (int r = 0; r < HW; r++) {
        int pb = r & 1;
        int cb = pb ^ 1;
        const float* hp = hbuf + pb * C1 * HSTR;
        float*       hn = hbuf + cb * C1 * HSTR;
        uint32_t hn_su = hbuf_su + (uint32_t)(cb * C1 * HSTR) * 4u;

        float pre[4][4];
        if (active) {
            int gb = (b * GG) * HW2 + r * HW + wg;
#pragma unroll
            for (int ty = 0; ty < 4; ty++)
#pragma unroll
                for (int cc = 0; cc < 4; cc++)
                    pre[ty][cc] = __ldcg(&g_i2s[gb + (ty * 64 + ch0 + cc) * HW2]);
        }

        u64 aA[4], aB[4];
#pragma unroll
        for (int ty = 0; ty < 4; ty++) { aA[ty] = 0ull; aB[ty] = 0ull; }

#pragma unroll 4
        for (int c = 0; c < C1; c++) {
            const float* hr = &hp[c * HSTR + lane];
            float h0 = hr[0], h1 = hr[1], h2 = hr[2];
            u64 s0 = pk2(h0, h0), s1 = pk2(h1, h1), s2 = pk2(h2, h2);
            const u64* wk = &wP[(c * 3) * 128 + (wid << 1)];
#pragma unroll
            for (int ty = 0; ty < 4; ty++) {
                ulonglong2 u0 = *(const ulonglong2*)(wk + ty * 32);
                ulonglong2 u1 = *(const ulonglong2*)(wk + ty * 32 + 128);
                ulonglong2 u2 = *(const ulonglong2*)(wk + ty * 32 + 256);
                fma2(aA[ty], u0.x, s0);  fma2(aB[ty], u0.y, s0);
                fma2(aA[ty], u1.x, s1);  fma2(aB[ty], u1.y, s1);
                fma2(aA[ty], u2.x, s2);  fma2(aB[ty], u2.y, s2);
            }
        }

        if (active) {
            float gate[4][4];
#pragma unroll
            for (int ty = 0; ty < 4; ty++) {
                unpk2(aA[ty], gate[ty][0], gate[ty][1]);
                unpk2(aB[ty], gate[ty][2], gate[ty][3]);
            }
#pragma unroll
            for (int cc = 0; cc < 4; cc++) {
                float go = gate[0][cc] + pre[0][cc];
                float gf = gate[1][cc] + pre[1][cc];
                float gi = gate[2][cc] + pre[2][cc];
                float gg = gate[3][cc] + pre[3][cc];
                float cn = sigmf(gf) * cst[cc] + sigmf(gi) * tanha(gg);
                float hv = sigmf(go) * tanha(cn);
                cst[cc] = cn;
                int ch = ch0 + cc;
                hn[ch * HSTR + lane + 1] = hv;
                out[((b * C1 + ch) * HW + r) * HW + wg] = hv;
                if (lane == 0 && jr > 0)
                    st_dsmem(hn_su + (uint32_t)(ch * HSTR + 32) * 4u, jr - 1, hv);
                if (lane == Ws - 1 && jr < CLU - 1)
                    st_dsmem(hn_su + (uint32_t)(ch * HSTR + 0) * 4u, jr + 1, hv);
            }
        }

        asm volatile("barrier.cluster.arrive.aligned;" ::: "memory");
        asm volatile("barrier.cluster.wait.aligned;"   ::: "memory");
    }
}

// ---------------- launch ----------------
extern "C" void kernel_launch(void* const* d_in, const int* in_sizes, int n_in,
                              void* d_out, int out_size)
{
    const float* x   = (const float*)d_in[0];
    const float* c1w = (const float*)d_in[1];
    const float* c1b = (const float*)d_in[2];
    const float* i2w = (const float*)d_in[3];
    const float* i2b = (const float*)d_in[4];
    const float* s2w = (const float*)d_in[5];
    const float* s2b = (const float*)d_in[6];
    float* out = (float*)d_out;

    const int i2s_smem  = (C1 * FSTR + 128 * WSTR + 128) * sizeof(float);   // ~133 KB
    const int scan_smem = 192 * 128 * 8 + 2 * C1 * HSTR * 4;                // ~210 KB
    cudaFuncSetAttribute(i2s_kernel,  cudaFuncAttributeMaxDynamicSharedMemorySize, i2s_smem);
    cudaFuncSetAttribute(scan_kernel, cudaFuncAttributeMaxDynamicSharedMemorySize, scan_smem);

    conv1_kernel<<<BB * HW, 256>>>(x, c1w, c1b);
    i2s_kernel<<<BB * HW * 2, 256, i2s_smem>>>(i2w, i2b, s2b);
    scan_kernel<<<BB * CLU, 512, scan_smem>>>(s2w, out);
}

// round 12
// speedup vs baseline: 1.8031x; 1.4739x over previous
#include <cuda_runtime.h>
#include <cstdint>

#define BB   32
#define C1   64
#define GG   256
#define HW   122
#define W0IN 128
#define CLU  4      // width slices (CTAs) per batch
#define WSL  31     // nominal slice width (last slice = 29)
#define FSTR 136    // i2s feat smem stride
#define WSTR 196    // tf32 weight smem stride (==4 mod 32 -> conflict-free A frags)
#define HSTR 40     // scan h-buffer stride (==8 mod 32 -> conflict-free B frags)

typedef unsigned long long u64;

// ---------------- scratch (static __device__: allocation-free) ----------------
__device__ float g_feat[BB * C1 * HW * HW];        // ~122 MB
__device__ float g_i2s[BB * GG * HW * HW];         // ~488 MB, layout [b][gate][h][w]

// ---------------- math helpers ----------------
__device__ __forceinline__ float tanha(float x) {
    float y;
    asm("tanh.approx.f32 %0, %1;" : "=f"(y) : "f"(x));
    return y;
}
__device__ __forceinline__ float sigmf(float x) {
    return 0.5f * tanha(0.5f * x) + 0.5f;
}
__device__ __forceinline__ uint32_t smem_u32(const void* p) {
    uint32_t a;
    asm("{ .reg .u64 tt; cvta.to.shared.u64 tt, %1; cvt.u32.u64 %0, tt; }"
        : "=r"(a) : "l"(p));
    return a;
}
__device__ __forceinline__ void st_dsmem(uint32_t laddr, uint32_t rank, float v) {
    asm volatile(
        "{ .reg .b32 ra; mapa.shared::cluster.u32 ra, %0, %1; "
        "st.shared::cluster.f32 [ra], %2; }"
        :: "r"(laddr), "r"(rank), "f"(v) : "memory");
}
__device__ __forceinline__ float tf32r(float x) {
    uint32_t u;
    asm("cvt.rna.tf32.f32 %0, %1;" : "=r"(u) : "f"(x));
    return __uint_as_float(u);
}
__device__ __forceinline__ void mma_tf32(float* d,
    uint32_t a0, uint32_t a1, uint32_t a2, uint32_t a3, uint32_t b0, uint32_t b1)
{
    asm volatile(
        "mma.sync.aligned.m16n8k8.row.col.f32.tf32.tf32.f32 "
        "{%0,%1,%2,%3}, {%4,%5,%6,%7}, {%8,%9}, {%0,%1,%2,%3};"
        : "+f"(d[0]), "+f"(d[1]), "+f"(d[2]), "+f"(d[3])
        : "r"(a0), "r"(a1), "r"(a2), "r"(a3), "r"(b0), "r"(b1));
}

// ---------------- conv1: 7x7 valid (R9 verbatim) ----------------
__global__ __launch_bounds__(256) void conv1_kernel(
    const float* __restrict__ x, const float* __restrict__ w1, const float* __restrict__ b1)
{
    __shared__ float xs[7][136];
    __shared__ float ws[C1 * 49];
    __shared__ float bs[C1];

    int bh = blockIdx.x;
    int b = bh / HW, h = bh % HW;
    int t = threadIdx.x;

    for (int i = t; i < C1 * 49; i += 256) ws[i] = w1[i];
    if (t < C1) bs[t] = b1[t];
    for (int i = t; i < 7 * 136; i += 256) {
        int r = i / 136, cw = i % 136;
        xs[r][cw] = (cw < W0IN) ? x[(b * W0IN + (h + r)) * W0IN + cw] : 0.f;
    }
    __syncthreads();

    for (int task = t; task < C1 * 32; task += 256) {
        int c = task >> 5;
        int wt = task & 31;
        int w0 = wt * 4;
        float a0 = 0.f, a1 = 0.f, a2 = 0.f, a3 = 0.f;
#pragma unroll
        for (int kh = 0; kh < 7; kh++) {
            float4 va = *(const float4*)&xs[kh][w0];
            float4 vb = *(const float4*)&xs[kh][w0 + 4];
            float2 vc = *(const float2*)&xs[kh][w0 + 8];
            float f[10] = {va.x, va.y, va.z, va.w, vb.x, vb.y, vb.z, vb.w, vc.x, vc.y};
            const float* wr = &ws[c * 49 + kh * 7];
#pragma unroll
            for (int kw = 0; kw < 7; kw++) {
                float wv = wr[kw];
                a0 += wv * f[kw];
                a1 += wv * f[kw + 1];
                a2 += wv * f[kw + 2];
                a3 += wv * f[kw + 3];
            }
        }
        float bb = bs[c];
        int base = ((b * C1 + c) * HW + h) * HW + w0;
        if (w0 + 0 < HW) g_feat[base + 0] = a0 + bb;
        if (w0 + 1 < HW) g_feat[base + 1] = a1 + bb;
        if (w0 + 2 < HW) g_feat[base + 2] = a2 + bb;
        if (w0 + 3 < HW) g_feat[base + 3] = a3 + bb;
    }
}

// ---------------- i2s: tf32 tensor-core GEMM (R9 verbatim) ----------------
__global__ __launch_bounds__(256) void i2s_kernel(
    const float* __restrict__ w, const float* __restrict__ bi, const float* __restrict__ bs2)
{
    extern __shared__ float sm[];
    float* fp  = sm;                     // [64][FSTR]
    float* wsm = sm + C1 * FSTR;         // [128][WSTR]
    float* bc  = wsm + 128 * WSTR;       // [128]

    int bx = blockIdx.x;
    int half = bx & 1;
    int bh = bx >> 1;
    int b = bh / HW, h = bh % HW;
    int t = threadIdx.x;

    for (int i = t; i < C1 * FSTR; i += 256) fp[i] = 0.f;
    __syncthreads();
    for (int i = t; i < C1 * HW; i += 256) {
        int c = i / HW, cw = i % HW;
        fp[c * FSTR + 1 + cw] = tf32r(g_feat[((b * C1 + c) * HW + h) * HW + cw]);
    }
    for (int i = t; i < 128 * 192; i += 256) {
        int m = i / 192, kp = i % 192;
        int dx = kp >> 6, c = kp & 63;
        wsm[m * WSTR + kp] = tf32r(w[(half * 128 + m) * 192 + c * 3 + dx]);
    }
    if (t < 128) {
        int og = half * 128 + t;
        bc[t] = bi[og] + bs2[og];
    }
    __syncthreads();

    int wid  = t >> 5;
    int lane = t & 31;
    int m0 = wid * 16;
    int qr = lane >> 2;
    int q  = lane & 3;

    const float* Ar0 = wsm + (m0 + qr) * WSTR;
    const float* Ar1 = wsm + (m0 + qr + 8) * WSTR;

    float d[16][4];
#pragma unroll
    for (int nt = 0; nt < 16; nt++)
#pragma unroll
        for (int i = 0; i < 4; i++) d[nt][i] = 0.f;

#pragma unroll
    for (int ks = 0; ks < 24; ks++) {
        int dx = ks >> 3;
        int cb = (ks & 7) * 8;
        int kb = ks * 8;
        uint32_t a0 = __float_as_uint(Ar0[kb + q]);
        uint32_t a1 = __float_as_uint(Ar1[kb + q]);
        uint32_t a2 = __float_as_uint(Ar0[kb + q + 4]);
        uint32_t a3 = __float_as_uint(Ar1[kb + q + 4]);
        const float* B0 = fp + (cb + q) * FSTR + dx + qr;
        const float* B1 = fp + (cb + q + 4) * FSTR + dx + qr;
#pragma unroll
        for (int nt = 0; nt < 16; nt++) {
            uint32_t b0 = __float_as_uint(B0[nt * 8]);
            uint32_t b1 = __float_as_uint(B1[nt * 8]);
            mma_tf32(d[nt], a0, a1, a2, a3, b0, b1);
        }
    }

    const int HW2 = HW * HW;
    int og0 = half * 128 + m0 + qr;
    int og1 = og0 + 8;
    float bb0 = bc[m0 + qr];
    float bb1 = bc[m0 + qr + 8];
    float* o0 = &g_i2s[((size_t)(b * GG + og0)) * HW2 + h * HW];
    float* o1 = &g_i2s[((size_t)(b * GG + og1)) * HW2 + h * HW];
#pragma unroll
    for (int nt = 0; nt < 16; nt++) {
        int col = nt * 8 + q * 2;
        if (col < HW) {
            *(float2*)(o0 + col) = make_float2(d[nt][0] + bb0, d[nt][1] + bb0);
            *(float2*)(o1 + col) = make_float2(d[nt][2] + bb1, d[nt][3] + bb1);
        }
    }
}

// ---------------- persistent scan v7: tf32 GEMM + warp-shuffle gate exchange ----
// Cluster = batch (4 CTAs, slices 31/31/31/29). 512 threads, 1 CTA/SM.
// Weight ROWS permuted so warp wid's 16-row m-tile = 4 channels x 4 gate types
// of channels wid*4..wid*4+3: row mrow = cl*2 + (ty&1) + 8*(ty>>1). The 4 gate
// types of a (channel, w) cell then live in lanes l and l^4 -> one 8-value
// shfl.bfly replaces the smem gate transpose (saves 18 KB smem + 3 syncs/row).
// smem 210,944 B — below every historically passing config.
__global__ __launch_bounds__(512, 1) __cluster_dims__(CLU, 1, 1)
void scan_kernel(const float* __restrict__ ws2, float* __restrict__ out)
{
    extern __shared__ float sm[];
    float* wsm  = sm;                          // [256][WSTR] 200704 B
    float* hbuf = sm + 256 * WSTR;             // [64][HSTR]  10240 B (cols 34..37 = halo slots)

    int t  = threadIdx.x;
    int bx = blockIdx.x;
    int b  = bx / CLU;
    int jr = bx % CLU;
    int ws_off = jr * WSL;
    int Ws = (jr == CLU - 1) ? (HW - (CLU - 1) * WSL) : WSL;   // 31/31/31/29

    // permuted tf32 weights: row m = wid*16 + mrow, mrow = cl*2+(ty&1)+8*(ty>>1),
    // gate g = ty*64 + wid*4 + cl; col kp = dx*64 + c <- ws2[g*192 + c*3 + dx]
    for (int i = t; i < 256 * 192; i += 512) {
        int m = i / 192, kp = i % 192;
        int dx = kp >> 6, c = kp & 63;
        int wq = m >> 4, mrow = m & 15;
        int tyhi = mrow >> 3, rem = mrow & 7;
        int cl = rem >> 1, tylo = rem & 1;
        int g = (tyhi * 2 + tylo) * 64 + wq * 4 + cl;
        wsm[m * WSTR + kp] = tf32r(ws2[g * 192 + c * 3 + dx]);
    }
    for (int i = t; i < C1 * HSTR; i += 512) hbuf[i] = 0.f;
    __syncthreads();
    asm volatile("barrier.cluster.arrive.aligned;" ::: "memory");
    asm volatile("barrier.cluster.wait.aligned;"   ::: "memory");

    int wid  = t >> 5;
    int lane = t & 31;
    int qr = lane >> 2;
    int q  = lane & 3;
    const float* Ar0 = wsm + (wid * 16 + qr) * WSTR;
    const float* Ar1 = Ar0 + 8 * WSTR;

    int tt = qr & 1;              // low type bit: rows hold types {tt, tt+2}
    int ch = wid * 4 + (qr >> 1); // this thread's channel
    uint32_t hbuf_su = smem_u32(hbuf);
    float cst[4] = {0.f, 0.f, 0.f, 0.f};   // c state per cell (k*2+j)
    const int HW2 = HW * HW;

    for (int r = 0; r < HW; r++) {
        int pb = r & 1, cb = pb ^ 1;

        // ---- prefetch i2s gates for my 4 cells (hidden under the GEMM)
        float pre[4][4];              // [type][cell]
#pragma unroll
        for (int k = 0; k < 2; k++)
#pragma unroll
            for (int j = 0; j < 2; j++) {
                int wcol = (tt * 2 + k) * 8 + q * 2 + j;
                int cell = k * 2 + j;
                if (wcol < Ws) {
                    const float* gp = &g_i2s[((size_t)(b * GG + ch)) * HW2 + r * HW + ws_off + wcol];
#pragma unroll
                    for (int ty = 0; ty < 4; ty++)
                        pre[ty][cell] = __ldcg(gp + (size_t)ty * 64 * HW2);
                } else {
#pragma unroll
                    for (int ty = 0; ty < 4; ty++) pre[ty][cell] = 0.f;
                }
            }

        // ---- install halo columns for row r (from parity slot pb)
        if (t < 128) {
            int c = t & 63, side = t >> 6;          // 0 = left (col 0), 1 = right (col Ws+1)
            float v = hbuf[c * HSTR + 34 + pb * 2 + side];
            hbuf[c * HSTR + (side ? (Ws + 1) : 0)] = v;
        }
        __syncthreads();

        // ---- GEMM: D[256 permuted gates][32 w] = W @ Hshift
        float d[4][4];
#pragma unroll
        for (int nt = 0; nt < 4; nt++)
#pragma unroll
            for (int i = 0; i < 4; i++) d[nt][i] = 0.f;

#pragma unroll
        for (int ks = 0; ks < 24; ks++) {
            int dx = ks >> 3;
            int cbk = (ks & 7) * 8;
            int kb = ks * 8;
            uint32_t a0 = __float_as_uint(Ar0[kb + q]);
            uint32_t a1 = __float_as_uint(Ar1[kb + q]);
            uint32_t a2 = __float_as_uint(Ar0[kb + q + 4]);
            uint32_t a3 = __float_as_uint(Ar1[kb + q + 4]);
            const float* B0 = hbuf + (cbk + q) * HSTR + dx + qr;
            const float* B1 = B0 + 4 * HSTR;
#pragma unroll
            for (int nt = 0; nt < 4; nt++) {
                uint32_t b0 = __float_as_uint(B0[nt * 8]);
                uint32_t b1 = __float_as_uint(B1[nt * 8]);
                mma_tf32(d[nt], a0, a1, a2, a3, b0, b1);
            }
        }

        // ---- exchange other two gate types with lane^4 (same channel, other tt)
        float ex[2][4];
#pragma unroll
        for (int k = 0; k < 2; k++)
#pragma unroll
            for (int i = 0; i < 4; i++) {
                float sendv = tt ? d[k][i] : d[2 + k][i];   // values for partner's nt pair
                ex[k][i] = __shfl_xor_sync(0xffffffffu, sendv, 4);
            }

        __syncthreads();   // all GEMM reads of hbuf complete before h overwrite

        // ---- LSTM epilogue: 4 cells (k, j), types assembled from own + exchanged
#pragma unroll
        for (int k = 0; k < 2; k++) {
            const float* ownd = tt ? d[2 + k] : d[k];       // my nt-pair values
#pragma unroll
            for (int j = 0; j < 2; j++) {
                int wcol = (tt * 2 + k) * 8 + q * 2 + j;
                if (wcol >= Ws) continue;
                int cell = k * 2 + j;
                float v_t  = ownd[j];        // type tt
                float v_t2 = ownd[2 + j];    // type tt+2
                float v_x  = ex[k][j];       // type 1-tt
                float v_x2 = ex[k][2 + j];   // type 3-tt
                float go = (tt ? v_x  : v_t ) + pre[0][cell];
                float gf = (tt ? v_t  : v_x ) + pre[1][cell];
                float gi = (tt ? v_x2 : v_t2) + pre[2][cell];
                float gg = (tt ? v_t2 : v_x2) + pre[3][cell];
                float cn = sigmf(gf) * cst[cell] + sigmf(gi) * tanha(gg);
                float hv = sigmf(go) * tanha(cn);
                cst[cell] = cn;
                float ht = tf32r(hv);
                hbuf[ch * HSTR + wcol + 1] = ht;
                out[((b * C1 + ch) * HW + r) * HW + ws_off + wcol] = hv;
                if (wcol == 0 && jr > 0)
                    st_dsmem(hbuf_su + (uint32_t)(ch * HSTR + 34 + cb * 2 + 1) * 4u, jr - 1, ht);
                if (wcol == Ws - 1 && jr < CLU - 1)
                    st_dsmem(hbuf_su + (uint32_t)(ch * HSTR + 34 + cb * 2 + 0) * 4u, jr + 1, ht);
            }
        }

        asm volatile("barrier.cluster.arrive.aligned;" ::: "memory");
        asm volatile("barrier.cluster.wait.aligned;"   ::: "memory");
    }
}

// ---------------- launch ----------------
extern "C" void kernel_launch(void* const* d_in, const int* in_sizes, int n_in,
                              void* d_out, int out_size)
{
    const float* x   = (const float*)d_in[0];
    const float* c1w = (const float*)d_in[1];
    const float* c1b = (const float*)d_in[2];
    const float* i2w = (const float*)d_in[3];
    const float* i2b = (const float*)d_in[4];
    const float* s2w = (const float*)d_in[5];
    const float* s2b = (const float*)d_in[6];
    float* out = (float*)d_out;

    const int i2s_smem  = (C1 * FSTR + 128 * WSTR + 128) * sizeof(float);    // ~133 KB
    const int scan_smem = (256 * WSTR + C1 * HSTR) * sizeof(float);          // 210944 B
    cudaFuncSetAttribute(i2s_kernel,  cudaFuncAttributeMaxDynamicSharedMemorySize, i2s_smem);
    cudaFuncSetAttribute(scan_kernel, cudaFuncAttributeMaxDynamicSharedMemorySize, scan_smem);

    conv1_kernel<<<BB * HW, 256>>>(x, c1w, c1b);
    i2s_kernel<<<BB * HW * 2, 256, i2s_smem>>>(i2w, i2b, s2b);
    scan_kernel<<<BB * CLU, 512, scan_smem>>>(s2w, out);
}

// round 14
// speedup vs baseline: 2.1962x; 1.2180x over previous
#include <cuda_runtime.h>
#include <cstdint>

#define BB   32
#define C1   64
#define GG   256
#define HW   122
#define W0IN 128
#define CLU  4      // width slices (CTAs) per batch
#define WSL  31     // nominal slice width (last slice = 29)
#define FSTR 136    // i2s feat smem stride
#define WSTR 196    // i2s tf32 weight smem stride (==4 mod 32)
#define WSW  100    // scan bf16 weight stride in WORDS (==4 mod 32)
#define HBW  40     // scan packed h-buffer stride in WORDS (==8 mod 32)

// ---------------- scratch (static __device__: allocation-free) ----------------
__device__ float g_feat[BB * C1 * HW * HW];        // ~122 MB
__device__ float g_i2s[BB * GG * HW * HW];         // ~488 MB, layout [b][gate][h][w]

// ---------------- math helpers ----------------
__device__ __forceinline__ float tanha(float x) {
    float y;
    asm("tanh.approx.f32 %0, %1;" : "=f"(y) : "f"(x));
    return y;
}
__device__ __forceinline__ float sigmf(float x) {
    return 0.5f * tanha(0.5f * x) + 0.5f;
}
__device__ __forceinline__ uint32_t smem_u32(const void* p) {
    uint32_t a;
    asm("{ .reg .u64 tt; cvta.to.shared.u64 tt, %1; cvt.u32.u64 %0, tt; }"
        : "=r"(a) : "l"(p));
    return a;
}
__device__ __forceinline__ float tf32r(float x) {
    uint32_t u;
    asm("cvt.rna.tf32.f32 %0, %1;" : "=r"(u) : "f"(x));
    return __uint_as_float(u);
}
__device__ __forceinline__ void mma_tf32(float* d,
    uint32_t a0, uint32_t a1, uint32_t a2, uint32_t a3, uint32_t b0, uint32_t b1)
{
    asm volatile(
        "mma.sync.aligned.m16n8k8.row.col.f32.tf32.tf32.f32 "
        "{%0,%1,%2,%3}, {%4,%5,%6,%7}, {%8,%9}, {%0,%1,%2,%3};"
        : "+f"(d[0]), "+f"(d[1]), "+f"(d[2]), "+f"(d[3])
        : "r"(a0), "r"(a1), "r"(a2), "r"(a3), "r"(b0), "r"(b1));
}
__device__ __forceinline__ void mma_bf16(float* d,
    uint32_t a0, uint32_t a1, uint32_t a2, uint32_t a3, uint32_t b0, uint32_t b1)
{
    asm volatile(
        "mma.sync.aligned.m16n8k16.row.col.f32.bf16.bf16.f32 "
        "{%0,%1,%2,%3}, {%4,%5,%6,%7}, {%8,%9}, {%0,%1,%2,%3};"
        : "+f"(d[0]), "+f"(d[1]), "+f"(d[2]), "+f"(d[3])
        : "r"(a0), "r"(a1), "r"(a2), "r"(a3), "r"(b0), "r"(b1));
}
__device__ __forceinline__ uint32_t pkbf2(float lo, float hi) {   // word = {hi,lo}
    uint32_t r;
    asm("cvt.rn.bf16x2.f32 %0, %1, %2;" : "=r"(r) : "f"(hi), "f"(lo));
    return r;
}
__device__ __forceinline__ uint16_t bf16b(float x) {
    uint16_t h;
    asm("cvt.rn.bf16.f32 %0, %1;" : "=h"(h) : "f"(x));
    return h;
}
__device__ __forceinline__ void sts16(uint32_t addr, uint16_t v) {
    asm volatile("st.shared.b16 [%0], %1;" :: "r"(addr), "h"(v) : "memory");
}
__device__ __forceinline__ void st_dsmem16(uint32_t laddr, uint32_t rank, uint16_t v) {
    asm volatile(
        "{ .reg .b32 ra; mapa.shared::cluster.u32 ra, %0, %1; "
        "st.shared::cluster.b16 [ra], %2; }"
        :: "r"(laddr), "r"(rank), "h"(v) : "memory");
}

// ---------------- conv1: 7x7 valid (R12 verbatim) ----------------
__global__ __launch_bounds__(256) void conv1_kernel(
    const float* __restrict__ x, const float* __restrict__ w1, const float* __restrict__ b1)
{
    __shared__ float xs[7][136];
    __shared__ float ws[C1 * 49];
    __shared__ float bs[C1];

    int bh = blockIdx.x;
    int b = bh / HW, h = bh % HW;
    int t = threadIdx.x;

    for (int i = t; i < C1 * 49; i += 256) ws[i] = w1[i];
    if (t < C1) bs[t] = b1[t];
    for (int i = t; i < 7 * 136; i += 256) {
        int r = i / 136, cw = i % 136;
        xs[r][cw] = (cw < W0IN) ? x[(b * W0IN + (h + r)) * W0IN + cw] : 0.f;
    }
    __syncthreads();

    for (int task = t; task < C1 * 32; task += 256) {
        int c = task >> 5;
        int wt = task & 31;
        int w0 = wt * 4;
        float a0 = 0.f, a1 = 0.f, a2 = 0.f, a3 = 0.f;
#pragma unroll
        for (int kh = 0; kh < 7; kh++) {
            float4 va = *(const float4*)&xs[kh][w0];
            float4 vb = *(const float4*)&xs[kh][w0 + 4];
            float2 vc = *(const float2*)&xs[kh][w0 + 8];
            float f[10] = {va.x, va.y, va.z, va.w, vb.x, vb.y, vb.z, vb.w, vc.x, vc.y};
            const float* wr = &ws[c * 49 + kh * 7];
#pragma unroll
            for (int kw = 0; kw < 7; kw++) {
                float wv = wr[kw];
                a0 += wv * f[kw];
                a1 += wv * f[kw + 1];
                a2 += wv * f[kw + 2];
                a3 += wv * f[kw + 3];
            }
        }
        float bb = bs[c];
        int base = ((b * C1 + c) * HW + h) * HW + w0;
        if (w0 + 0 < HW) g_feat[base + 0] = a0 + bb;
        if (w0 + 1 < HW) g_feat[base + 1] = a1 + bb;
        if (w0 + 2 < HW) g_feat[base + 2] = a2 + bb;
        if (w0 + 3 < HW) g_feat[base + 3] = a3 + bb;
    }
}

// ---------------- i2s: tf32 tensor-core GEMM (R12 verbatim) ----------------
__global__ __launch_bounds__(256) void i2s_kernel(
    const float* __restrict__ w, const float* __restrict__ bi, const float* __restrict__ bs2)
{
    extern __shared__ float sm[];
    float* fp  = sm;                     // [64][FSTR]
    float* wsm = sm + C1 * FSTR;         // [128][WSTR]
    float* bc  = wsm + 128 * WSTR;       // [128]

    int bx = blockIdx.x;
    int half = bx & 1;
    int bh = bx >> 1;
    int b = bh / HW, h = bh % HW;
    int t = threadIdx.x;

    for (int i = t; i < C1 * FSTR; i += 256) fp[i] = 0.f;
    __syncthreads();
    for (int i = t; i < C1 * HW; i += 256) {
        int c = i / HW, cw = i % HW;
        fp[c * FSTR + 1 + cw] = tf32r(g_feat[((b * C1 + c) * HW + h) * HW + cw]);
    }
    for (int i = t; i < 128 * 192; i += 256) {
        int m = i / 192, kp = i % 192;
        int dx = kp >> 6, c = kp & 63;
        wsm[m * WSTR + kp] = tf32r(w[(half * 128 + m) * 192 + c * 3 + dx]);
    }
    if (t < 128) {
        int og = half * 128 + t;
        bc[t] = bi[og] + bs2[og];
    }
    __syncthreads();

    int wid  = t >> 5;
    int lane = t & 31;
    int m0 = wid * 16;
    int qr = lane >> 2;
    int q  = lane & 3;

    const float* Ar0 = wsm + (m0 + qr) * WSTR;
    const float* Ar1 = wsm + (m0 + qr + 8) * WSTR;

    float d[16][4];
#pragma unroll
    for (int nt = 0; nt < 16; nt++)
#pragma unroll
        for (int i = 0; i < 4; i++) d[nt][i] = 0.f;

#pragma unroll
    for (int ks = 0; ks < 24; ks++) {
        int dx = ks >> 3;
        int cb = (ks & 7) * 8;
        int kb = ks * 8;
        uint32_t a0 = __float_as_uint(Ar0[kb + q]);
        uint32_t a1 = __float_as_uint(Ar1[kb + q]);
        uint32_t a2 = __float_as_uint(Ar0[kb + q + 4]);
        uint32_t a3 = __float_as_uint(Ar1[kb + q + 4]);
        const float* B0 = fp + (cb + q) * FSTR + dx + qr;
        const float* B1 = fp + (cb + q + 4) * FSTR + dx + qr;
#pragma unroll
        for (int nt = 0; nt < 16; nt++) {
            uint32_t b0 = __float_as_uint(B0[nt * 8]);
            uint32_t b1 = __float_as_uint(B1[nt * 8]);
            mma_tf32(d[nt], a0, a1, a2, a3, b0, b1);
        }
    }

    const int HW2 = HW * HW;
    int og0 = half * 128 + m0 + qr;
    int og1 = og0 + 8;
    float bb0 = bc[m0 + qr];
    float bb1 = bc[m0 + qr + 8];
    float* o0 = &g_i2s[((size_t)(b * GG + og0)) * HW2 + h * HW];
    float* o1 = &g_i2s[((size_t)(b * GG + og1)) * HW2 + h * HW];
#pragma unroll
    for (int nt = 0; nt < 16; nt++) {
        int col = nt * 8 + q * 2;
        if (col < HW) {
            *(float2*)(o0 + col) = make_float2(d[nt][0] + bb0, d[nt][1] + bb0);
            *(float2*)(o1 + col) = make_float2(d[nt][2] + bb1, d[nt][3] + bb1);
        }
    }
}

// ---------------- persistent scan v8b: bf16 m16n8k16 s2s GEMM (B-row fix) -------
// Identical to R13 except the B-fragment row index: cpair = (ks&3)*8 + q
// (the dx block shifts columns, not rows). smem 107,520 B.
__global__ __launch_bounds__(512, 1) __cluster_dims__(CLU, 1, 1)
void scan_kernel(const float* __restrict__ ws2, float* __restrict__ out)
{
    extern __shared__ uint32_t smu[];
    uint32_t* wsm = smu;                       // [256][WSW]  bf16-pair words
    uint32_t* hb  = smu + 256 * WSW;           // [32][HBW]   packed h (cols 34..37 = halo)

    int t  = threadIdx.x;
    int bx = blockIdx.x;
    int b  = bx / CLU;
    int jr = bx % CLU;
    int ws_off = jr * WSL;
    int Ws = (jr == CLU - 1) ? (HW - (CLU - 1) * WSL) : WSL;   // 31/31/31/29

    // permuted bf16 weights: row m = wq*16 + mrow, mrow = cl*2+tylo+8*tyhi,
    // gate g = (tyhi*2+tylo)*64 + wq*4 + cl; word kw = dx*32 + c/2 packs (c, c+1)
    for (int i = t; i < 256 * 96; i += 512) {
        int m = i / 96, kw = i % 96;
        int dx = kw >> 5, c = (kw & 31) * 2;
        int wq = m >> 4, mrow = m & 15;
        int tyhi = mrow >> 3, rem = mrow & 7;
        int cl = rem >> 1, tylo = rem & 1;
        int g = (tyhi * 2 + tylo) * 64 + wq * 4 + cl;
        wsm[m * WSW + kw] = pkbf2(ws2[g * 192 + c * 3 + dx],
                                  ws2[g * 192 + (c + 1) * 3 + dx]);
    }
    for (int i = t; i < 32 * HBW; i += 512) hb[i] = 0u;
    __syncthreads();
    asm volatile("barrier.cluster.arrive.aligned;" ::: "memory");
    asm volatile("barrier.cluster.wait.aligned;"   ::: "memory");

    int wid  = t >> 5;
    int lane = t & 31;
    int qr = lane >> 2;
    int q  = lane & 3;
    const uint32_t* Ar0 = wsm + (wid * 16 + qr) * WSW;
    const uint32_t* Ar1 = Ar0 + 8 * WSW;

    int tt = qr & 1;              // low type bit: rows hold types {tt, tt+2}
    int ch = wid * 4 + (qr >> 1); // this thread's channel
    uint32_t hb_su = smem_u32(hb);
    float cst[4] = {0.f, 0.f, 0.f, 0.f};
    const int HW2 = HW * HW;

    for (int r = 0; r < HW; r++) {
        int pb = r & 1, cb = pb ^ 1;

        // ---- prefetch i2s gates for my 4 cells (hidden under the GEMM)
        float pre[4][4];              // [type][cell]
#pragma unroll
        for (int k = 0; k < 2; k++)
#pragma unroll
            for (int j = 0; j < 2; j++) {
                int wcol = (tt * 2 + k) * 8 + q * 2 + j;
                int cell = k * 2 + j;
                if (wcol < Ws) {
                    const float* gp = &g_i2s[((size_t)(b * GG + ch)) * HW2 + r * HW + ws_off + wcol];
#pragma unroll
                    for (int ty = 0; ty < 4; ty++)
                        pre[ty][cell] = __ldcg(gp + (size_t)ty * 64 * HW2);
                } else {
#pragma unroll
                    for (int ty = 0; ty < 4; ty++) pre[ty][cell] = 0.f;
                }
            }

        // ---- install halo words for row r (from parity slot pb)
        if (t < 64) {
            int cp = t & 31, side = t >> 5;          // 0 = left (col 0), 1 = right (col Ws+1)
            uint32_t v = hb[cp * HBW + 34 + pb * 2 + side];
            hb[cp * HBW + (side ? (Ws + 1) : 0)] = v;
        }
        __syncthreads();

        // ---- GEMM: D[256 permuted gates][32 w] = W @ Hshift, bf16 K=16
        float d[4][4];
#pragma unroll
        for (int nt = 0; nt < 4; nt++)
#pragma unroll
            for (int i = 0; i < 4; i++) d[nt][i] = 0.f;

#pragma unroll
        for (int ks = 0; ks < 12; ks++) {
            int dx = ks >> 2;
            int kb = ks * 8;                    // A-side word base (96 words/row)
            int cpb = (ks & 3) * 8;             // B-side cpair row base (32 rows)
            uint32_t a0 = Ar0[kb + q];
            uint32_t a1 = Ar1[kb + q];
            uint32_t a2 = Ar0[kb + q + 4];
            uint32_t a3 = Ar1[kb + q + 4];
            const uint32_t* B0 = hb + (cpb + q) * HBW + dx + qr;
            const uint32_t* B1 = B0 + 4 * HBW;
#pragma unroll
            for (int nt = 0; nt < 4; nt++) {
                uint32_t b0 = B0[nt * 8];
                uint32_t b1 = B1[nt * 8];
                mma_bf16(d[nt], a0, a1, a2, a3, b0, b1);
            }
        }

        // ---- exchange other two gate types with lane^4 (same channel, other tt)
        float ex[2][4];
#pragma unroll
        for (int k = 0; k < 2; k++)
#pragma unroll
            for (int i = 0; i < 4; i++) {
                float sendv = tt ? d[k][i] : d[2 + k][i];
                ex[k][i] = __shfl_xor_sync(0xffffffffu, sendv, 4);
            }

        __syncthreads();   // all GEMM reads of hb complete before h overwrite

        // ---- LSTM epilogue: 4 cells (k, j)
#pragma unroll
        for (int k = 0; k < 2; k++) {
            const float* ownd = tt ? d[2 + k] : d[k];
#pragma unroll
            for (int j = 0; j < 2; j++) {
                int wcol = (tt * 2 + k) * 8 + q * 2 + j;
                if (wcol >= Ws) continue;
                int cell = k * 2 + j;
                float v_t  = ownd[j];
                float v_t2 = ownd[2 + j];
                float v_x  = ex[k][j];
                float v_x2 = ex[k][2 + j];
                float go = (tt ? v_x  : v_t ) + pre[0][cell];
                float gf = (tt ? v_t  : v_x ) + pre[1][cell];
                float gi = (tt ? v_x2 : v_t2) + pre[2][cell];
                float gg = (tt ? v_t2 : v_x2) + pre[3][cell];
                float cn = sigmf(gf) * cst[cell] + sigmf(gi) * tanha(gg);
                float hv = sigmf(go) * tanha(cn);
                cst[cell] = cn;
                uint16_t hbits = bf16b(hv);
                // local packed store: row ch>>1, col wcol+1, half ch&1
                sts16(hb_su + (uint32_t)(((ch >> 1) * HBW + wcol + 1) << 2)
                            + (uint32_t)((ch & 1) << 1), hbits);
                out[((b * C1 + ch) * HW + r) * HW + ws_off + wcol] = hv;
                if (wcol == 0 && jr > 0)
                    st_dsmem16(hb_su + (uint32_t)(((ch >> 1) * HBW + 34 + cb * 2 + 1) << 2)
                                     + (uint32_t)((ch & 1) << 1), jr - 1, hbits);
                if (wcol == Ws - 1 && jr < CLU - 1)
                    st_dsmem16(hb_su + (uint32_t)(((ch >> 1) * HBW + 34 + cb * 2 + 0) << 2)
                                     + (uint32_t)((ch & 1) << 1), jr + 1, hbits);
            }
        }

        asm volatile("barrier.cluster.arrive.aligned;" ::: "memory");
        asm volatile("barrier.cluster.wait.aligned;"   ::: "memory");
    }
}

// ---------------- launch ----------------
extern "C" void kernel_launch(void* const* d_in, const int* in_sizes, int n_in,
                              void* d_out, int out_size)
{
    const float* x   = (const float*)d_in[0];
    const float* c1w = (const float*)d_in[1];
    const float* c1b = (const float*)d_in[2];
    const float* i2w = (const float*)d_in[3];
    const float* i2b = (const float*)d_in[4];
    const float* s2w = (const float*)d_in[5];
    const float* s2b = (const float*)d_in[6];
    float* out = (float*)d_out;

    const int i2s_smem  = (C1 * FSTR + 128 * WSTR + 128) * sizeof(float);    // ~133 KB
    const int scan_smem = (256 * WSW + 32 * HBW) * 4;                        // 107,520 B
    cudaFuncSetAttribute(i2s_kernel,  cudaFuncAttributeMaxDynamicSharedMemorySize, i2s_smem);
    cudaFuncSetAttribute(scan_kernel, cudaFuncAttributeMaxDynamicSharedMemorySize, scan_smem);

    conv1_kernel<<<BB * HW, 256>>>(x, c1w, c1b);
    i2s_kernel<<<BB * HW * 2, 256, i2s_smem>>>(i2w, i2b, s2b);
    scan_kernel<<<BB * CLU, 512, scan_smem>>>(s2w, out);
}

// round 15
// speedup vs baseline: 2.2116x; 1.0070x over previous
#include <cuda_runtime.h>
#include <cstdint>

#define BB   32
#define C1   64
#define GG   256
#define HW   122
#define W0IN 128
#define CLU  4      // width slices (CTAs) per batch
#define WSL  31     // nominal slice width (last slice = 29)
#define FSTR 136    // i2s feat smem stride
#define WSTR 196    // i2s tf32 weight smem stride (==4 mod 32)
#define WSW  100    // scan bf16 weight stride in WORDS (==4 mod 32)
#define HBW  40     // scan packed h-buffer stride in WORDS (==8 mod 32)

// ---------------- scratch (static __device__: allocation-free) ----------------
__device__ float g_feat[BB * C1 * HW * HW];        // ~122 MB
__device__ float g_i2s[BB * GG * HW * HW];         // ~488 MB, layout [b][gate][h][w]

// ---------------- math helpers ----------------
__device__ __forceinline__ float tanha(float x) {
    float y;
    asm("tanh.approx.f32 %0, %1;" : "=f"(y) : "f"(x));
    return y;
}
__device__ __forceinline__ float sigmf(float x) {
    return 0.5f * tanha(0.5f * x) + 0.5f;
}
__device__ __forceinline__ uint32_t smem_u32(const void* p) {
    uint32_t a;
    asm("{ .reg .u64 tt; cvta.to.shared.u64 tt, %1; cvt.u32.u64 %0, tt; }"
        : "=r"(a) : "l"(p));
    return a;
}
__device__ __forceinline__ float tf32r(float x) {
    uint32_t u;
    asm("cvt.rna.tf32.f32 %0, %1;" : "=r"(u) : "f"(x));
    return __uint_as_float(u);
}
__device__ __forceinline__ void mma_tf32(float* d,
    uint32_t a0, uint32_t a1, uint32_t a2, uint32_t a3, uint32_t b0, uint32_t b1)
{
    asm volatile(
        "mma.sync.aligned.m16n8k8.row.col.f32.tf32.tf32.f32 "
        "{%0,%1,%2,%3}, {%4,%5,%6,%7}, {%8,%9}, {%0,%1,%2,%3};"
        : "+f"(d[0]), "+f"(d[1]), "+f"(d[2]), "+f"(d[3])
        : "r"(a0), "r"(a1), "r"(a2), "r"(a3), "r"(b0), "r"(b1));
}
__device__ __forceinline__ void mma_bf16(float* d,
    uint32_t a0, uint32_t a1, uint32_t a2, uint32_t a3, uint32_t b0, uint32_t b1)
{
    asm volatile(
        "mma.sync.aligned.m16n8k16.row.col.f32.bf16.bf16.f32 "
        "{%0,%1,%2,%3}, {%4,%5,%6,%7}, {%8,%9}, {%0,%1,%2,%3};"
        : "+f"(d[0]), "+f"(d[1]), "+f"(d[2]), "+f"(d[3])
        : "r"(a0), "r"(a1), "r"(a2), "r"(a3), "r"(b0), "r"(b1));
}
__device__ __forceinline__ uint32_t pkbf2(float lo, float hi) {   // word = {hi,lo}
    uint32_t r;
    asm("cvt.rn.bf16x2.f32 %0, %1, %2;" : "=r"(r) : "f"(hi), "f"(lo));
    return r;
}
__device__ __forceinline__ uint16_t bf16b(float x) {
    uint16_t h;
    asm("cvt.rn.bf16.f32 %0, %1;" : "=h"(h) : "f"(x));
    return h;
}
__device__ __forceinline__ void sts16(uint32_t addr, uint16_t v) {
    asm volatile("st.shared.b16 [%0], %1;" :: "r"(addr), "h"(v) : "memory");
}
__device__ __forceinline__ void st_dsmem16(uint32_t laddr, uint32_t rank, uint16_t v) {
    asm volatile(
        "{ .reg .b32 ra; mapa.shared::cluster.u32 ra, %0, %1; "
        "st.shared::cluster.b16 [ra], %2; }"
        :: "r"(laddr), "r"(rank), "h"(v) : "memory");
}

// ---------------- conv1: 7x7 valid (R14 verbatim) ----------------
__global__ __launch_bounds__(256) void conv1_kernel(
    const float* __restrict__ x, const float* __restrict__ w1, const float* __restrict__ b1)
{
    __shared__ float xs[7][136];
    __shared__ float ws[C1 * 49];
    __shared__ float bs[C1];

    int bh = blockIdx.x;
    int b = bh / HW, h = bh % HW;
    int t = threadIdx.x;

    for (int i = t; i < C1 * 49; i += 256) ws[i] = w1[i];
    if (t < C1) bs[t] = b1[t];
    for (int i = t; i < 7 * 136; i += 256) {
        int r = i / 136, cw = i % 136;
        xs[r][cw] = (cw < W0IN) ? x[(b * W0IN + (h + r)) * W0IN + cw] : 0.f;
    }
    __syncthreads();

    for (int task = t; task < C1 * 32; task += 256) {
        int c = task >> 5;
        int wt = task & 31;
        int w0 = wt * 4;
        float a0 = 0.f, a1 = 0.f, a2 = 0.f, a3 = 0.f;
#pragma unroll
        for (int kh = 0; kh < 7; kh++) {
            float4 va = *(const float4*)&xs[kh][w0];
            float4 vb = *(const float4*)&xs[kh][w0 + 4];
            float2 vc = *(const float2*)&xs[kh][w0 + 8];
            float f[10] = {va.x, va.y, va.z, va.w, vb.x, vb.y, vb.z, vb.w, vc.x, vc.y};
            const float* wr = &ws[c * 49 + kh * 7];
#pragma unroll
            for (int kw = 0; kw < 7; kw++) {
                float wv = wr[kw];
                a0 += wv * f[kw];
                a1 += wv * f[kw + 1];
                a2 += wv * f[kw + 2];
                a3 += wv * f[kw + 3];
            }
        }
        float bb = bs[c];
        int base = ((b * C1 + c) * HW + h) * HW + w0;
        if (w0 + 0 < HW) g_feat[base + 0] = a0 + bb;
        if (w0 + 1 < HW) g_feat[base + 1] = a1 + bb;
        if (w0 + 2 < HW) g_feat[base + 2] = a2 + bb;
        if (w0 + 3 < HW) g_feat[base + 3] = a3 + bb;
    }
}

// ---------------- i2s: tf32 tensor-core GEMM (R14 verbatim) ----------------
__global__ __launch_bounds__(256) void i2s_kernel(
    const float* __restrict__ w, const float* __restrict__ bi, const float* __restrict__ bs2)
{
    extern __shared__ float sm[];
    float* fp  = sm;                     // [64][FSTR]
    float* wsm = sm + C1 * FSTR;         // [128][WSTR]
    float* bc  = wsm + 128 * WSTR;       // [128]

    int bx = blockIdx.x;
    int half = bx & 1;
    int bh = bx >> 1;
    int b = bh / HW, h = bh % HW;
    int t = threadIdx.x;

    for (int i = t; i < C1 * FSTR; i += 256) fp[i] = 0.f;
    __syncthreads();
    for (int i = t; i < C1 * HW; i += 256) {
        int c = i / HW, cw = i % HW;
        fp[c * FSTR + 1 + cw] = tf32r(g_feat[((b * C1 + c) * HW + h) * HW + cw]);
    }
    for (int i = t; i < 128 * 192; i += 256) {
        int m = i / 192, kp = i % 192;
        int dx = kp >> 6, c = kp & 63;
        wsm[m * WSTR + kp] = tf32r(w[(half * 128 + m) * 192 + c * 3 + dx]);
    }
    if (t < 128) {
        int og = half * 128 + t;
        bc[t] = bi[og] + bs2[og];
    }
    __syncthreads();

    int wid  = t >> 5;
    int lane = t & 31;
    int m0 = wid * 16;
    int qr = lane >> 2;
    int q  = lane & 3;

    const float* Ar0 = wsm + (m0 + qr) * WSTR;
    const float* Ar1 = wsm + (m0 + qr + 8) * WSTR;

    float d[16][4];
#pragma unroll
    for (int nt = 0; nt < 16; nt++)
#pragma unroll
        for (int i = 0; i < 4; i++) d[nt][i] = 0.f;

#pragma unroll
    for (int ks = 0; ks < 24; ks++) {
        int dx = ks >> 3;
        int cb = (ks & 7) * 8;
        int kb = ks * 8;
        uint32_t a0 = __float_as_uint(Ar0[kb + q]);
        uint32_t a1 = __float_as_uint(Ar1[kb + q]);
        uint32_t a2 = __float_as_uint(Ar0[kb + q + 4]);
        uint32_t a3 = __float_as_uint(Ar1[kb + q + 4]);
        const float* B0 = fp + (cb + q) * FSTR + dx + qr;
        const float* B1 = fp + (cb + q + 4) * FSTR + dx + qr;
#pragma unroll
        for (int nt = 0; nt < 16; nt++) {
            uint32_t b0 = __float_as_uint(B0[nt * 8]);
            uint32_t b1 = __float_as_uint(B1[nt * 8]);
            mma_tf32(d[nt], a0, a1, a2, a3, b0, b1);
        }
    }

    const int HW2 = HW * HW;
    int og0 = half * 128 + m0 + qr;
    int og1 = og0 + 8;
    float bb0 = bc[m0 + qr];
    float bb1 = bc[m0 + qr + 8];
    float* o0 = &g_i2s[((size_t)(b * GG + og0)) * HW2 + h * HW];
    float* o1 = &g_i2s[((size_t)(b * GG + og1)) * HW2 + h * HW];
#pragma unroll
    for (int nt = 0; nt < 16; nt++) {
        int col = nt * 8 + q * 2;
        if (col < HW) {
            *(float2*)(o0 + col) = make_float2(d[nt][0] + bb0, d[nt][1] + bb0);
            *(float2*)(o1 + col) = make_float2(d[nt][2] + bb1, d[nt][3] + bb1);
        }
    }
}

// ---------------- persistent scan v9: double-buffered h, zero intra-row syncs ----
// R14 architecture, but h is double-buffered (buf[r&1] = h(r)): the GEMM reads
// buf[(r+1)&1] while the epilogue writes buf[r&1] -> no post-GEMM sync. Edge
// values go via DSMEM straight into the neighbor's NEXT-row read buffer (left
// neighbor col 32, right neighbor col 0) -> no halo-install step, no pre-GEMM
// sync. The per-row cluster barrier (full execution+memory barrier for the
// cluster) provides all ordering. smem 112,640 B. Arithmetic identical to R14.
__global__ __launch_bounds__(512, 1) __cluster_dims__(CLU, 1, 1)
void scan_kernel(const float* __restrict__ ws2, float* __restrict__ out)
{
    extern __shared__ uint32_t smu[];
    uint32_t* wsm = smu;                       // [256][WSW]  bf16-pair words
    uint32_t* hb  = smu + 256 * WSW;           // [2][32][HBW] packed h, double-buffered

    int t  = threadIdx.x;
    int bx = blockIdx.x;
    int b  = bx / CLU;
    int jr = bx % CLU;
    int ws_off = jr * WSL;
    int Ws = (jr == CLU - 1) ? (HW - (CLU - 1) * WSL) : WSL;   // 31/31/31/29

    // permuted bf16 weights: row m = wq*16 + mrow, mrow = cl*2+tylo+8*tyhi,
    // gate g = (tyhi*2+tylo)*64 + wq*4 + cl; word kw = dx*32 + c/2 packs (c, c+1)
    for (int i = t; i < 256 * 96; i += 512) {
        int m = i / 96, kw = i % 96;
        int dx = kw >> 5, c = (kw & 31) * 2;
        int wq = m >> 4, mrow = m & 15;
        int tyhi = mrow >> 3, rem = mrow & 7;
        int cl = rem >> 1, tylo = rem & 1;
        int g = (tyhi * 2 + tylo) * 64 + wq * 4 + cl;
        wsm[m * WSW + kw] = pkbf2(ws2[g * 192 + c * 3 + dx],
                                  ws2[g * 192 + (c + 1) * 3 + dx]);
    }
    for (int i = t; i < 2 * 32 * HBW; i += 512) hb[i] = 0u;
    __syncthreads();
    asm volatile("barrier.cluster.arrive.aligned;" ::: "memory");
    asm volatile("barrier.cluster.wait.aligned;"   ::: "memory");

    int wid  = t >> 5;
    int lane = t & 31;
    int qr = lane >> 2;
    int q  = lane & 3;
    const uint32_t* Ar0 = wsm + (wid * 16 + qr) * WSW;
    const uint32_t* Ar1 = Ar0 + 8 * WSW;

    int tt = qr & 1;              // low type bit: rows hold types {tt, tt+2}
    int ch = wid * 4 + (qr >> 1); // this thread's channel
    uint32_t hb_su = smem_u32(hb);
    float cst[4] = {0.f, 0.f, 0.f, 0.f};
    const int HW2 = HW * HW;

    for (int r = 0; r < HW; r++) {
        int cb2 = r & 1;          // buffer receiving h(r)
        int pb2 = cb2 ^ 1;        // buffer holding h(r-1)
        const uint32_t* hrd = hb + pb2 * 32 * HBW;
        uint32_t cbase = hb_su + (uint32_t)(cb2 * 32 * HBW) * 4u;

        // ---- prefetch i2s gates for my 4 cells (hidden under the GEMM)
        float pre[4][4];              // [type][cell]
#pragma unroll
        for (int k = 0; k < 2; k++)
#pragma unroll
            for (int j = 0; j < 2; j++) {
                int wcol = (tt * 2 + k) * 8 + q * 2 + j;
                int cell = k * 2 + j;
                if (wcol < Ws) {
                    const float* gp = &g_i2s[((size_t)(b * GG + ch)) * HW2 + r * HW + ws_off + wcol];
#pragma unroll
                    for (int ty = 0; ty < 4; ty++)
                        pre[ty][cell] = __ldcg(gp + (size_t)ty * 64 * HW2);
                } else {
#pragma unroll
                    for (int ty = 0; ty < 4; ty++) pre[ty][cell] = 0.f;
                }
            }

        // ---- GEMM: D[256 permuted gates][32 w] = W @ Hshift, bf16 K=16
        float d[4][4];
#pragma unroll
        for (int nt = 0; nt < 4; nt++)
#pragma unroll
            for (int i = 0; i < 4; i++) d[nt][i] = 0.f;

#pragma unroll
        for (int ks = 0; ks < 12; ks++) {
            int dx = ks >> 2;
            int kb = ks * 8;                    // A-side word base (96 words/row)
            int cpb = (ks & 3) * 8;             // B-side cpair row base (32 rows)
            uint32_t a0 = Ar0[kb + q];
            uint32_t a1 = Ar1[kb + q];
            uint32_t a2 = Ar0[kb + q + 4];
            uint32_t a3 = Ar1[kb + q + 4];
            const uint32_t* B0 = hrd + (cpb + q) * HBW + dx + qr;
            const uint32_t* B1 = B0 + 4 * HBW;
#pragma unroll
            for (int nt = 0; nt < 4; nt++) {
                uint32_t b0 = B0[nt * 8];
                uint32_t b1 = B1[nt * 8];
                mma_bf16(d[nt], a0, a1, a2, a3, b0, b1);
            }
        }

        // ---- exchange other two gate types with lane^4 (same channel, other tt)
        float ex[2][4];
#pragma unroll
        for (int k = 0; k < 2; k++)
#pragma unroll
            for (int i = 0; i < 4; i++) {
                float sendv = tt ? d[k][i] : d[2 + k][i];
                ex[k][i] = __shfl_xor_sync(0xffffffffu, sendv, 4);
            }

        // ---- LSTM epilogue: 4 cells (k, j); writes go to the OTHER buffer
#pragma unroll
        for (int k = 0; k < 2; k++) {
            const float* ownd = tt ? d[2 + k] : d[k];
#pragma unroll
            for (int j = 0; j < 2; j++) {
                int wcol = (tt * 2 + k) * 8 + q * 2 + j;
                if (wcol >= Ws) continue;
                int cell = k * 2 + j;
                float v_t  = ownd[j];
                float v_t2 = ownd[2 + j];
                float v_x  = ex[k][j];
                float v_x2 = ex[k][2 + j];
                float go = (tt ? v_x  : v_t ) + pre[0][cell];
                float gf = (tt ? v_t  : v_x ) + pre[1][cell];
                float gi = (tt ? v_x2 : v_t2) + pre[2][cell];
                float gg = (tt ? v_t2 : v_x2) + pre[3][cell];
                float cn = sigmf(gf) * cst[cell] + sigmf(gi) * tanha(gg);
                float hv = sigmf(go) * tanha(cn);
                cst[cell] = cn;
                uint16_t hbits = bf16b(hv);
                // local packed store into buf[cb2]: row ch>>1, col wcol+1, half ch&1
                sts16(cbase + (uint32_t)(((ch >> 1) * HBW + wcol + 1) << 2)
                            + (uint32_t)((ch & 1) << 1), hbits);
                out[((b * C1 + ch) * HW + r) * HW + ws_off + wcol] = hv;
                // edges go straight into the neighbor's buf[cb2] halo columns
                if (wcol == 0 && jr > 0)                 // left neighbor (Ws=31) col 32
                    st_dsmem16(cbase + (uint32_t)(((ch >> 1) * HBW + 32) << 2)
                                     + (uint32_t)((ch & 1) << 1), jr - 1, hbits);
                if (wcol == Ws - 1 && jr < CLU - 1)      // right neighbor col 0
                    st_dsmem16(cbase + (uint32_t)(((ch >> 1) * HBW + 0) << 2)
                                     + (uint32_t)((ch & 1) << 1), jr + 1, hbits);
            }
        }

        // single per-row barrier: orders local STS + remote DSMEM cluster-wide
        asm volatile("barrier.cluster.arrive.aligned;" ::: "memory");
        asm volatile("barrier.cluster.wait.aligned;"   ::: "memory");
    }
}

// ---------------- launch ----------------
extern "C" void kernel_launch(void* const* d_in, const int* in_sizes, int n_in,
                              void* d_out, int out_size)
{
    const float* x   = (const float*)d_in[0];
    const float* c1w = (const float*)d_in[1];
    const float* c1b = (const float*)d_in[2];
    const float* i2w = (const float*)d_in[3];
    const float* i2b = (const float*)d_in[4];
    const float* s2w = (const float*)d_in[5];
    const float* s2b = (const float*)d_in[6];
    float* out = (float*)d_out;

    const int i2s_smem  = (C1 * FSTR + 128 * WSTR + 128) * sizeof(float);    // ~133 KB
    const int scan_smem = (256 * WSW + 2 * 32 * HBW) * 4;                    // 112,640 B
    cudaFuncSetAttribute(i2s_kernel,  cudaFuncAttributeMaxDynamicSharedMemorySize, i2s_smem);
    cudaFuncSetAttribute(scan_kernel, cudaFuncAttributeMaxDynamicSharedMemorySize, scan_smem);

    conv1_kernel<<<BB * HW, 256>>>(x, c1w, c1b);
    i2s_kernel<<<BB * HW * 2, 256, i2s_smem>>>(i2w, i2b, s2b);
    scan_kernel<<<BB * CLU, 512, scan_smem>>>(s2w, out);
}